// round 12
// baseline (speedup 1.0000x reference)
#include <cuda_runtime.h>
#include <cstdint>

#define BB 32
#define NI 512
#define NH 2048
#define NO 256
#define TT 1024

// ---------------- scratch (no allocations allowed) ----------------
__device__ uint32_t g_s1bits[BB * TT * 64];  // spk1 packed: [b][t][64 words] (8 MB)
__device__ float    g_w2t[NH * NO];          // w2 transposed: [i][o] (2 MB)
__device__ float    g_cur2[BB * NO * TT];    // layer-2 currents (32 MB)
__device__ uint16_t g_xidx[(size_t)BB * TT * 512];  // per-(b,t) active lists (32 MB)
__device__ int      g_xcnt[BB * TT];                // counts (128 KB)

#define BAR_SYNC(id, cnt)   asm volatile("bar.sync %0, %1;"   :: "r"(id), "r"(cnt) : "memory")
#define BAR_ARRIVE(id, cnt) asm volatile("bar.arrive %0, %1;" :: "r"(id), "r"(cnt) : "memory")
#define ADD_F32X2(acc, wv)  asm("add.rn.f32x2 %0, %1, %2;" : "=l"(acc) : "l"(acc), "l"(wv))

// ---------------- K1: build active-input index lists per (b,t) -----------
// Padded to 120 entries with index 512 (zero row in layer1 smem tile).
__global__ void k_build_lists(const float* __restrict__ x) {
    int bt = blockIdx.x * 256 + threadIdx.x;   // 32768 threads
    int b = bt >> 10, t = bt & 1023;
    const float* xp = x + ((size_t)b * NI) * TT + t;
    uint16_t* out = g_xidx + (size_t)bt * 512;
    int n = 0;
#pragma unroll 8
    for (int i = 0; i < NI; i++) {
        if (xp[(size_t)i * TT] > 0.5f) out[n++] = (uint16_t)i;
    }
    g_xcnt[bt] = n;
    for (int m = n; m < 120; m++) out[m] = 512;  // pad (skipped if n >= 120)
}

// ---------------- K0: transpose w2 (NO,NH) -> w2t (NH,NO) ----------------
__global__ void k_transpose_w2(const float* __restrict__ w2) {
    __shared__ float tile[32][33];
    int i0 = blockIdx.x * 32;
    int o0 = blockIdx.y * 32;
    int tx = threadIdx.x, ty = threadIdx.y;  // 32 x 8
    for (int r = ty; r < 32; r += 8)
        tile[r][tx] = w2[(size_t)(o0 + r) * NH + i0 + tx];
    __syncthreads();
    for (int r = ty; r < 32; r += 8)
        g_w2t[(size_t)(i0 + r) * NO + o0 + tx] = tile[tx][r];
}

// ---------------- no-op probe: keeps ncu slot on k_layer1 ----------------
__global__ void k_probe() {}

// ---------------- K2: fused layer1, quarter-warp, 2 CTAs/SM --------------
// 288 threads: tid 0..255 producers (8 warps), tid 256..287 consumer warp.
// Producer warp processes FOUR t's at once: lane group g = lane>>3 owns
// t = pass*32 + wid*4 + g; lane8 = lane&7 owns 4 outputs (o0 + lane8*4..+3)
// via one predicated LDS.128 + two add.rn.f32x2 per active. Predicated-off
// lanes (m >= n of their t) generate no crossbar traffic.
// w1s layout: [513][32] floats. XOR swizzle: quad q of row i at slot
// q^(i&7). Hot load: lane8 reads quad lane8^(i&7) of its row -> each 8-lane
// group covers one full 128B row, conflict-free. Row 512 = zeros.
// smem/CTA: w1s 65664 + curb 16384 + lidx 30720 + lcnt 512 = 113280 B
//           -> two CTAs per SM.
#define L1_SMEM (513 * 32 * 4 + 2 * 64 * 32 * 4 + 2 * 64 * 120 * 2 + 2 * 64 * 4)
#define NPROD 256
#define NTHR  288
// named barriers: FULL0=1, FULL1=2, FREE0=3, FREE1=4, PROD=5

__global__ void __launch_bounds__(NTHR, 2) k_layer1(
    const float* __restrict__ w1, const float* __restrict__ b1,
    float* __restrict__ spk1) {
    extern __shared__ float smem[];
    float* w1s = smem;                                   // [513][32] swizzled
    float* curb = smem + 513 * 32;                       // [2][64][32]
    uint16_t* lidx = (uint16_t*)(curb + 2 * 64 * 32);    // [2][64][120]
    int* lcnt = (int*)(lidx + 2 * 64 * 120);             // [2][64]

    int tid = threadIdx.x;
    int b = blockIdx.y;
    int o0 = blockIdx.x * 32;

    // stage w1 tile swizzled: output ol of row i -> quad (ol>>2)^(i&7), sub ol&3
    for (int idx = tid; idx < 32 * 512; idx += NTHR) {
        int ol = idx >> 9, i = idx & 511;
        int quad = (ol >> 2) ^ (i & 7);
        w1s[i * 32 + quad * 4 + (ol & 3)] = w1[(size_t)(o0 + ol) * NI + i];
    }
    if (tid < 32) w1s[512 * 32 + tid] = 0.0f;  // zero row (padding target)
    __syncthreads();

    if (tid < NPROD) {
        // ---------------- producers ----------------
        int wid = tid >> 5, lane = tid & 31;
        int g = lane >> 3, lane8 = lane & 7;
        float4 b4 = *(const float4*)&b1[o0 + lane8 * 4];
        uint64_t bias_lo, bias_hi;
        asm("mov.b64 %0, {%1, %2};" : "=l"(bias_lo)
            : "r"(__float_as_uint(b4.x)), "r"(__float_as_uint(b4.y)));
        asm("mov.b64 %0, {%1, %2};" : "=l"(bias_hi)
            : "r"(__float_as_uint(b4.z)), "r"(__float_as_uint(b4.w)));

        for (int k = 0; k < 16; k++) {
            int p = k & 1;
            size_t bt0 = (size_t)b * TT + k * 64;
            if (k >= 2) BAR_SYNC(3 + p, NTHR);  // wait curb[p] free

            // stage lists: 120 idx (60 words) per t, 64 t
            {
                const uint32_t* src = (const uint32_t*)(g_xidx + bt0 * 512);
                uint32_t* dst = (uint32_t*)(lidx + (size_t)p * 64 * 120);
                for (int m = tid; m < 64 * 60; m += NPROD) {
                    int tl = m / 60, c = m - tl * 60;
                    dst[m] = src[tl * 256 + c];
                }
                if (tid < 64) lcnt[p * 64 + tid] = g_xcnt[bt0 + tid];
            }
            BAR_SYNC(5, NPROD);  // producers only: staging visible

#pragma unroll 1
            for (int pass = 0; pass < 2; pass++) {
                int tc = pass * 32 + wid * 4 + g;   // this group's t
                int n = lcnt[p * 64 + tc];
                int nm = n;
                nm = max(nm, __shfl_xor_sync(0xffffffffu, nm, 8));
                nm = max(nm, __shfl_xor_sync(0xffffffffu, nm, 16));
                int bound = nm < 120 ? ((nm + 3) & ~3) : 120;
                const uint32_t* lp32 =
                    (const uint32_t*)lidx + (p * 64 + tc) * 60;
                uint64_t acc0 = bias_lo, acc1 = bias_hi;

#define WQUAD(i) (w1s + ((unsigned)(i) << 5) + ((lane8 ^ ((i) & 7u)) << 2))
#pragma unroll 1
                for (int m = 0; m < bound; m += 4) {
                    uint32_t q0 = lp32[m >> 1], q1 = lp32[(m >> 1) + 1];
                    uint32_t i0 = q0 & 0xffffu, i1 = q0 >> 16;
                    uint32_t i2 = q1 & 0xffffu, i3 = q1 >> 16;
                    ulonglong2 w0, w1v, w2v, w3;
                    w0.x = 0; w0.y = 0; w1v.x = 0; w1v.y = 0;
                    w2v.x = 0; w2v.y = 0; w3.x = 0; w3.y = 0;
                    if (m < n)     w0 = *(const ulonglong2*)WQUAD(i0);
                    if (m + 1 < n) w1v = *(const ulonglong2*)WQUAD(i1);
                    if (m + 2 < n) w2v = *(const ulonglong2*)WQUAD(i2);
                    if (m + 3 < n) w3 = *(const ulonglong2*)WQUAD(i3);
                    ADD_F32X2(acc0, w0.x); ADD_F32X2(acc1, w0.y);
                    ADD_F32X2(acc0, w1v.x); ADD_F32X2(acc1, w1v.y);
                    ADD_F32X2(acc0, w2v.x); ADD_F32X2(acc1, w2v.y);
                    ADD_F32X2(acc0, w3.x); ADD_F32X2(acc1, w3.y);
                }
                // extremely rare overflow (count > 120): exact fallback
                if (n > 120) {
                    for (int m = 120; m < n; m++) {
                        uint32_t i = g_xidx[(bt0 + tc) * 512 + m];
                        ulonglong2 wv = *(const ulonglong2*)WQUAD(i);
                        ADD_F32X2(acc0, wv.x); ADD_F32X2(acc1, wv.y);
                    }
                }
#undef WQUAD
                float* cb = &curb[(p * 64 + tc) * 32 + lane8 * 4];
                *(uint64_t*)cb = acc0;
                *(uint64_t*)(cb + 2) = acc1;
            }
            BAR_ARRIVE(1 + p, NTHR);  // curb[p] full
        }
    } else {
        // ---------------- consumer warp: LIF + writeout ----------------
        int n = tid - NPROD;      // neuron 0..31
        float v = 0.0f;
        uint32_t* s1base = g_s1bits + ((size_t)b * TT) * 64 + (o0 >> 5);

        for (int k = 0; k < 16; k++) {
            int p = k & 1;
            int t0 = k * 64;
            BAR_SYNC(1 + p, NTHR);  // wait curb[p] full

            uint32_t sp0 = 0, sp1 = 0;
#pragma unroll 1
            for (int tc = 0; tc < 64; tc++) {
                float c = curb[(p * 64 + tc) * 32 + n];
                v = v * 0.95f + c;
                bool fire = (v >= 1.0f);
                v = fire ? 0.0f : v;
                uint32_t bal = __ballot_sync(0xffffffffu, fire);
                if (n == 0) s1base[(size_t)(t0 + tc) * 64] = bal;
                if (tc < 32) sp0 |= (fire ? 1u : 0u) << tc;
                else         sp1 |= (fire ? 1u : 0u) << (tc - 32);
            }
            BAR_ARRIVE(3 + p, NTHR);  // curb[p] free (spikes now in regs)

            // coalesced writeout: warp walks its 32 rows, lanes cover t
#pragma unroll 1
            for (int r = 0; r < 32; r++) {
                uint32_t w0 = __shfl_sync(0xffffffffu, sp0, r);
                uint32_t w1b = __shfl_sync(0xffffffffu, sp1, r);
                int o = o0 + r;
                int tb = n * 2;
                uint64_t bits = ((uint64_t)w1b << 32) | (uint64_t)w0;
                float f0 = ((bits >> tb) & 1ull) ? 1.0f : 0.0f;
                float f1 = ((bits >> (tb + 1)) & 1ull) ? 1.0f : 0.0f;
                *(float2*)&spk1[((size_t)b * NH + o) * TT + t0 + tb] =
                    make_float2(f0, f1);
            }
        }
    }
}

// ---------------- K3: layer-2 currents (64-row chunks, 2 CTAs/SM) --------
#define L2_SMEM (64 * 256 * 4 + 64 * 2 * 4)

__global__ void __launch_bounds__(512, 2) k_layer2cur(const float* __restrict__ b2) {
    extern __shared__ float smem[];
    float* w2s = smem;                             // [i_local][o] 64*256
    uint32_t* sw = (uint32_t*)(smem + 64 * 256);   // [t_local][2]

    int tid = threadIdx.x;
    int b = blockIdx.y;
    int t0 = blockIdx.x * 64;
    int oq = (tid & 63) * 4;
    int th = tid >> 6;

    float acc[4][8];
    {
        const float* bp = b2 + oq;
        float bz0 = bp[0], bz1 = bp[1], bz2 = bp[2], bz3 = bp[3];
#pragma unroll
        for (int q = 0; q < 8; q++) {
            acc[0][q] = bz0; acc[1][q] = bz1; acc[2][q] = bz2; acc[3][q] = bz3;
        }
    }

#pragma unroll 1
    for (int kc = 0; kc < 32; kc++) {
        __syncthreads();
        {
            const float4* src = (const float4*)(g_w2t + (size_t)kc * 64 * NO);
            float4* dst = (float4*)w2s;
            for (int idx = tid; idx < 64 * 256 / 4; idx += 512)
                dst[idx] = src[idx];
        }
        if (tid < 128) {
            int t_l = tid >> 1, w = tid & 1;
            sw[tid] = g_s1bits[((size_t)b * TT + t0 + t_l) * 64 + kc * 2 + w];
        }
        __syncthreads();

#pragma unroll
        for (int q = 0; q < 8; q++) {
            const uint32_t* wp = sw + (th * 8 + q) * 2;
#pragma unroll
            for (int w = 0; w < 2; w++) {
                uint32_t word = wp[w];
                while (word) {
                    int j = __ffs(word) - 1;
                    word &= word - 1;
                    float4 wv = *(const float4*)&w2s[(w * 32 + j) * NO + oq];
                    acc[0][q] += wv.x; acc[1][q] += wv.y;
                    acc[2][q] += wv.z; acc[3][q] += wv.w;
                }
            }
        }
    }

#pragma unroll
    for (int k = 0; k < 4; k++) {
        float* dst = g_cur2 + ((size_t)b * NO + oq + k) * TT + t0 + th * 8;
        ((float4*)dst)[0] = make_float4(acc[k][0], acc[k][1], acc[k][2], acc[k][3]);
        ((float4*)dst)[1] = make_float4(acc[k][4], acc[k][5], acc[k][6], acc[k][7]);
    }
}

// ---------------- K4: LIF layer 2 (4-deep load batches) ------------------
__global__ void k_lif2(float* __restrict__ spk2) {
    int bo = blockIdx.x * 64 + threadIdx.x;  // 8192 sequences, 128 blocks
    const float4* cur = (const float4*)(g_cur2 + (size_t)bo * TT);
    float4* out = (float4*)(spk2 + (size_t)bo * TT);
    float v = 0.0f;
#pragma unroll 1
    for (int q = 0; q < TT / 4; q += 4) {
        float4 c0 = cur[q], c1 = cur[q + 1], c2 = cur[q + 2], c3 = cur[q + 3];
        float4 s;
#define LIFSTEP(cc, ss) \
        v = v * 0.95f + (cc); (ss) = (v >= 1.0f) ? 1.0f : 0.0f; v = (v >= 1.0f) ? 0.0f : v;
        LIFSTEP(c0.x, s.x) LIFSTEP(c0.y, s.y) LIFSTEP(c0.z, s.z) LIFSTEP(c0.w, s.w)
        out[q] = s;
        LIFSTEP(c1.x, s.x) LIFSTEP(c1.y, s.y) LIFSTEP(c1.z, s.z) LIFSTEP(c1.w, s.w)
        out[q + 1] = s;
        LIFSTEP(c2.x, s.x) LIFSTEP(c2.y, s.y) LIFSTEP(c2.z, s.z) LIFSTEP(c2.w, s.w)
        out[q + 2] = s;
        LIFSTEP(c3.x, s.x) LIFSTEP(c3.y, s.y) LIFSTEP(c3.z, s.z) LIFSTEP(c3.w, s.w)
        out[q + 3] = s;
#undef LIFSTEP
    }
}

// ---------------- launch ----------------
extern "C" void kernel_launch(void* const* d_in, const int* in_sizes, int n_in,
                              void* d_out, int out_size) {
    (void)in_sizes; (void)n_in; (void)out_size;
    const float* x  = (const float*)d_in[0];
    const float* w1 = (const float*)d_in[1];
    const float* b1 = (const float*)d_in[2];
    const float* w2 = (const float*)d_in[3];
    const float* b2 = (const float*)d_in[4];

    float* spk1 = (float*)d_out;                        // (32,2048,1024)
    float* spk2 = spk1 + (size_t)BB * NH * TT;          // (32,256,1024)

    cudaFuncSetAttribute(k_layer1, cudaFuncAttributeMaxDynamicSharedMemorySize, L1_SMEM);
    cudaFuncSetAttribute(k_layer2cur, cudaFuncAttributeMaxDynamicSharedMemorySize, L2_SMEM);

    k_build_lists<<<BB * TT / 256, 256>>>(x);
    k_transpose_w2<<<dim3(NH / 32, NO / 32), dim3(32, 8)>>>(w2);
    k_probe<<<1, 32>>>();  // keeps ncu's captured slot on k_layer1
    k_layer1<<<dim3(NH / 32, BB), NTHR, L1_SMEM>>>(w1, b1, spk1);
    k_layer2cur<<<dim3(TT / 64, BB), 512, L2_SMEM>>>(b2);
    k_lif2<<<BB * NO / 64, 64>>>(spk2);
}